// round 2
// baseline (speedup 1.0000x reference)
#include <cuda_runtime.h>

// SepKANLayer1D: per-token KAN edge-spline layer, 4 tokens per thread (float4).
// x: (4, 8, 65536) f32, w: (4, 640, 65536) f32, out: (4, 8, 65536) f32.
// Pure HBM-streaming: every w element read exactly once, fully coalesced LDG.128.

#define IN_C   8
#define OUT_C  8
#define NB     8
#define NTOK   65536
#define ROW    (NTOK / 4)       // row stride in float4 units = 16384
#define WSIZE  640

__global__ __launch_bounds__(128)
void sepkan_kernel(const float4* __restrict__ x4,
                   const float4* __restrict__ w4,
                   float4* __restrict__ out4) {
    const int t = blockIdx.x * blockDim.x + threadIdx.x;   // 0 .. 65535 (token-quad id)
    const int b = t >> 14;                                 // 16384 quads per batch
    const int q = t & (ROW - 1);                           // quad index within batch row

    const float4* xp = x4 + (size_t)b * IN_C * ROW + q;
    const float4* wp = w4 + (size_t)b * WSIZE * ROW + q;

    float acc[OUT_C][4];
#pragma unroll
    for (int o = 0; o < OUT_C; ++o)
#pragma unroll
        for (int l = 0; l < 4; ++l) acc[o][l] = 0.0f;

#pragma unroll 1   // keep code size bounded; each iteration has 74 independent LDG.128
    for (int i = 0; i < IN_C; ++i) {
        const float4 xv = __ldg(xp + i * ROW);
        float xi[4] = {xv.x, xv.y, xv.z, xv.w};

        // ---- Cox-de Boor, degree 0..3, uniform knots t_j = -0.6 + 0.2*j ----
        float bs[11][4];
#pragma unroll
        for (int j = 0; j < 11; ++j) {
            const float t0 = -0.6f + 0.2f * (float)j;
            const float t1 = t0 + 0.2f;
#pragma unroll
            for (int l = 0; l < 4; ++l)
                bs[j][l] = (xi[l] >= t0 && xi[l] < t1) ? 1.0f : 0.0f;
        }
#pragma unroll
        for (int p = 1; p <= 3; ++p) {
            const float inv = 1.0f / (0.2f * (float)p);
#pragma unroll
            for (int j = 0; j < 11 - p; ++j) {
                const float tj   = -0.6f + 0.2f * (float)j;
                const float tjp1 = -0.6f + 0.2f * (float)(j + p + 1);
#pragma unroll
                for (int l = 0; l < 4; ++l)
                    bs[j][l] = (xi[l] - tj) * inv * bs[j][l]
                             + (tjp1 - xi[l]) * inv * bs[j + 1][l];
            }
        }
        // bs[0..7][l] are the 8 cubic basis values per token lane.

        float sx[4];
#pragma unroll
        for (int l = 0; l < 4; ++l)
            sx[l] = xi[l] / (1.0f + __expf(-xi[l]));       // silu

        const float4* wc = wp + (size_t)(i * OUT_C * NB) * ROW;
        const float4* wu = wp + (size_t)(IN_C * OUT_C * NB + i * OUT_C) * ROW;
        const float4* wr = wp + (size_t)(IN_C * OUT_C * NB + IN_C * OUT_C + i * OUT_C) * ROW;

#pragma unroll
        for (int o = 0; o < OUT_C; ++o) {
            float sp[4] = {0.0f, 0.0f, 0.0f, 0.0f};
#pragma unroll
            for (int k = 0; k < NB; ++k) {
                const float4 c = __ldg(wc + (size_t)(o * NB + k) * ROW);
                sp[0] = fmaf(bs[k][0], c.x, sp[0]);
                sp[1] = fmaf(bs[k][1], c.y, sp[1]);
                sp[2] = fmaf(bs[k][2], c.z, sp[2]);
                sp[3] = fmaf(bs[k][3], c.w, sp[3]);
            }
            const float4 u = __ldg(wu + (size_t)o * ROW);
            const float4 r = __ldg(wr + (size_t)o * ROW);
            acc[o][0] = fmaf(u.x, sp[0], acc[o][0]);
            acc[o][1] = fmaf(u.y, sp[1], acc[o][1]);
            acc[o][2] = fmaf(u.z, sp[2], acc[o][2]);
            acc[o][3] = fmaf(u.w, sp[3], acc[o][3]);
            acc[o][0] = fmaf(sx[0], r.x, acc[o][0]);
            acc[o][1] = fmaf(sx[1], r.y, acc[o][1]);
            acc[o][2] = fmaf(sx[2], r.z, acc[o][2]);
            acc[o][3] = fmaf(sx[3], r.w, acc[o][3]);
        }
    }

    float4* yp = out4 + (size_t)b * OUT_C * ROW + q;
#pragma unroll
    for (int o = 0; o < OUT_C; ++o) {
        float4 v;
        v.x = acc[o][0]; v.y = acc[o][1]; v.z = acc[o][2]; v.w = acc[o][3];
        yp[(size_t)o * ROW] = v;
    }
}

extern "C" void kernel_launch(void* const* d_in, const int* in_sizes, int n_in,
                              void* d_out, int out_size) {
    const float4* x = (const float4*)d_in[0];   // (4, 8, 65536)
    const float4* w = (const float4*)d_in[1];   // (4, 640, 65536)
    float4* out = (float4*)d_out;               // (4, 8, 65536)

    const int quads = 4 * NTOK / 4;             // 65536 threads
    const int threads = 128;
    const int blocks = quads / threads;         // 512
    sepkan_kernel<<<blocks, threads>>>(x, w, out);
}

// round 3
// speedup vs baseline: 1.2114x; 1.2114x over previous
#include <cuda_runtime.h>

// SepKANLayer1D: per-token KAN edge-spline layer. 1 token/thread, scalar LDG.
// x: (4, 8, 65536) f32, w: (4, 640, 65536) f32, out: (4, 8, 65536) f32.
// Pure HBM stream: w read exactly once -> __ldcs (evict-first), max occupancy.

#define IN_C   8
#define OUT_C  8
#define NB     8
#define NTOK   65536
#define WSIZE  640

__global__ __launch_bounds__(128, 16)   // force regs<=32, 64 warps/SM
void sepkan_kernel(const float* __restrict__ x,
                   const float* __restrict__ w,
                   float* __restrict__ out) {
    const int t = blockIdx.x * blockDim.x + threadIdx.x;   // 0 .. 262143
    const int b = t >> 16;
    const int n = t & (NTOK - 1);

    const float* xp = x + (size_t)b * IN_C * NTOK + n;
    const float* wp = w + (size_t)b * WSIZE * NTOK + n;

    float acc[OUT_C];
#pragma unroll
    for (int o = 0; o < OUT_C; ++o) acc[o] = 0.0f;

#pragma unroll 1   // bounded code size; ~82 independent loads per iteration
    for (int i = 0; i < IN_C; ++i) {
        const float xi = __ldg(xp + i * NTOK);

        // ---- Cox-de Boor, degree 0..3, uniform knots t_j = -0.6 + 0.2*j ----
        float bs[11];
#pragma unroll
        for (int j = 0; j < 11; ++j) {
            const float t0 = -0.6f + 0.2f * (float)j;
            const float t1 = t0 + 0.2f;
            bs[j] = (xi >= t0 && xi < t1) ? 1.0f : 0.0f;
        }
#pragma unroll
        for (int p = 1; p <= 3; ++p) {
            const float inv = 1.0f / (0.2f * (float)p);
#pragma unroll
            for (int j = 0; j < 11 - p; ++j) {
                const float tj   = -0.6f + 0.2f * (float)j;
                const float tjp1 = -0.6f + 0.2f * (float)(j + p + 1);
                bs[j] = (xi - tj) * inv * bs[j] + (tjp1 - xi) * inv * bs[j + 1];
            }
        }
        // bs[0..7] are the 8 cubic basis values.

        const float sx = xi / (1.0f + __expf(-xi));   // silu

        const float* wc = wp + (size_t)(i * OUT_C * NB) * NTOK;
        const float* wu = wp + (size_t)(IN_C * OUT_C * NB + i * OUT_C) * NTOK;
        const float* wr = wp + (size_t)(IN_C * OUT_C * NB + IN_C * OUT_C + i * OUT_C) * NTOK;

#pragma unroll
        for (int o = 0; o < OUT_C; ++o) {
            float sp = 0.0f;
#pragma unroll
            for (int k = 0; k < NB; ++k)
                sp = fmaf(bs[k], __ldcs(wc + (size_t)(o * NB + k) * NTOK), sp);
            acc[o] = fmaf(__ldcs(wu + (size_t)o * NTOK), sp, acc[o]);
            acc[o] = fmaf(sx, __ldcs(wr + (size_t)o * NTOK), acc[o]);
        }
    }

    float* yp = out + (size_t)b * OUT_C * NTOK + n;
#pragma unroll
    for (int o = 0; o < OUT_C; ++o)
        yp[(size_t)o * NTOK] = acc[o];
}

extern "C" void kernel_launch(void* const* d_in, const int* in_sizes, int n_in,
                              void* d_out, int out_size) {
    const float* x = (const float*)d_in[0];   // (4, 8, 65536)
    const float* w = (const float*)d_in[1];   // (4, 640, 65536)
    float* out = (float*)d_out;               // (4, 8, 65536)

    const int total = 4 * NTOK;               // 262144 tokens
    const int threads = 128;
    const int blocks = total / threads;       // 2048
    sepkan_kernel<<<blocks, threads>>>(x, w, out);
}

// round 4
// speedup vs baseline: 1.2977x; 1.0713x over previous
#include <cuda_runtime.h>

// SepKANLayer1D: per-token KAN edge-spline layer.
// x: (4, 8, 65536) f32, w: (4, 640, 65536) f32, out: (4, 8, 65536) f32.
// Pure HBM stream: w read exactly once -> __ldcs. 2 threads per token
// (o-halves, via blockIdx.y) to reach full warp occupancy chip-wide.

#define IN_C   8
#define OUT_C  8
#define NB     8
#define OH     4                // outputs per thread
#define NTOK   65536
#define WSIZE  640

__global__ __launch_bounds__(128, 16)
void sepkan_kernel(const float* __restrict__ x,
                   const float* __restrict__ w,
                   float* __restrict__ out) {
    const int t = blockIdx.x * blockDim.x + threadIdx.x;   // 0 .. 262143 (token id)
    const int ob = blockIdx.y * OH;                        // 0 or 4: output-channel base
    const int b = t >> 16;
    const int n = t & (NTOK - 1);

    const float* xp = x + (size_t)b * IN_C * NTOK + n;
    const float* wp = w + (size_t)b * WSIZE * NTOK + n;

    float acc[OH];
#pragma unroll
    for (int oo = 0; oo < OH; ++oo) acc[oo] = 0.0f;

#pragma unroll 1   // bounded code size; ~41 independent loads per iteration
    for (int i = 0; i < IN_C; ++i) {
        const float xi = __ldg(xp + i * NTOK);

        // ---- Cox-de Boor, degree 0..3, uniform knots t_j = -0.6 + 0.2*j ----
        float bs[11];
#pragma unroll
        for (int j = 0; j < 11; ++j) {
            const float t0 = -0.6f + 0.2f * (float)j;
            const float t1 = t0 + 0.2f;
            bs[j] = (xi >= t0 && xi < t1) ? 1.0f : 0.0f;
        }
#pragma unroll
        for (int p = 1; p <= 3; ++p) {
            const float inv = 1.0f / (0.2f * (float)p);
#pragma unroll
            for (int j = 0; j < 11 - p; ++j) {
                const float tj   = -0.6f + 0.2f * (float)j;
                const float tjp1 = -0.6f + 0.2f * (float)(j + p + 1);
                bs[j] = (xi - tj) * inv * bs[j] + (tjp1 - xi) * inv * bs[j + 1];
            }
        }
        // bs[0..7] are the 8 cubic basis values.

        const float sx = xi / (1.0f + __expf(-xi));   // silu

        const float* wc = wp + (size_t)(i * OUT_C * NB + ob * NB) * NTOK;
        const float* wu = wp + (size_t)(IN_C * OUT_C * NB + i * OUT_C + ob) * NTOK;
        const float* wr = wp + (size_t)(IN_C * OUT_C * NB + IN_C * OUT_C + i * OUT_C + ob) * NTOK;

#pragma unroll
        for (int oo = 0; oo < OH; ++oo) {
            float sp = 0.0f;
#pragma unroll
            for (int k = 0; k < NB; ++k)
                sp = fmaf(bs[k], __ldcs(wc + (size_t)(oo * NB + k) * NTOK), sp);
            acc[oo] = fmaf(__ldcs(wu + (size_t)oo * NTOK), sp, acc[oo]);
            acc[oo] = fmaf(sx, __ldcs(wr + (size_t)oo * NTOK), acc[oo]);
        }
    }

    float* yp = out + ((size_t)b * OUT_C + ob) * NTOK + n;
#pragma unroll
    for (int oo = 0; oo < OH; ++oo)
        yp[(size_t)oo * NTOK] = acc[oo];
}

extern "C" void kernel_launch(void* const* d_in, const int* in_sizes, int n_in,
                              void* d_out, int out_size) {
    const float* x = (const float*)d_in[0];   // (4, 8, 65536)
    const float* w = (const float*)d_in[1];   // (4, 640, 65536)
    float* out = (float*)d_out;               // (4, 8, 65536)

    const int total = 4 * NTOK;               // 262144 tokens
    dim3 grid(total / 128, OUT_C / OH);       // (2048, 2)
    sepkan_kernel<<<grid, 128>>>(x, w, out);
}

// round 5
// speedup vs baseline: 1.3220x; 1.0187x over previous
#include <cuda_runtime.h>

// SepKANLayer1D: per-token KAN edge-spline layer.
// x: (4, 8, 65536) f32, w: (4, 640, 65536) f32, out: (4, 8, 65536) f32.
// Pure HBM stream: w read exactly once -> __ldcs. 4 threads per token
// (o-quarters, via blockIdx.y) to maximize resident-warp latency hiding.

#define IN_C   8
#define OUT_C  8
#define NB     8
#define OH     2                // outputs per thread
#define NTOK   65536
#define WSIZE  640

__global__ __launch_bounds__(128, 16)
void sepkan_kernel(const float* __restrict__ x,
                   const float* __restrict__ w,
                   float* __restrict__ out) {
    const int t = blockIdx.x * blockDim.x + threadIdx.x;   // 0 .. 262143 (token id)
    const int ob = blockIdx.y * OH;                        // 0,2,4,6: output-channel base
    const int b = t >> 16;
    const int n = t & (NTOK - 1);

    const float* xp = x + (size_t)b * IN_C * NTOK + n;
    const float* wp = w + (size_t)b * WSIZE * NTOK + n;

    float acc[OH];
#pragma unroll
    for (int oo = 0; oo < OH; ++oo) acc[oo] = 0.0f;

#pragma unroll 1   // bounded code size; ~21 independent loads per iteration
    for (int i = 0; i < IN_C; ++i) {
        const float xi = __ldg(xp + i * NTOK);

        // ---- Cox-de Boor, degree 0..3, uniform knots t_j = -0.6 + 0.2*j ----
        float bs[11];
#pragma unroll
        for (int j = 0; j < 11; ++j) {
            const float t0 = -0.6f + 0.2f * (float)j;
            const float t1 = t0 + 0.2f;
            bs[j] = (xi >= t0 && xi < t1) ? 1.0f : 0.0f;
        }
#pragma unroll
        for (int p = 1; p <= 3; ++p) {
            const float inv = 1.0f / (0.2f * (float)p);
#pragma unroll
            for (int j = 0; j < 11 - p; ++j) {
                const float tj   = -0.6f + 0.2f * (float)j;
                const float tjp1 = -0.6f + 0.2f * (float)(j + p + 1);
                bs[j] = (xi - tj) * inv * bs[j] + (tjp1 - xi) * inv * bs[j + 1];
            }
        }
        // bs[0..7] are the 8 cubic basis values.

        const float sx = xi / (1.0f + __expf(-xi));   // silu

        const float* wc = wp + (size_t)(i * OUT_C * NB + ob * NB) * NTOK;
        const float* wu = wp + (size_t)(IN_C * OUT_C * NB + i * OUT_C + ob) * NTOK;
        const float* wr = wp + (size_t)(IN_C * OUT_C * NB + IN_C * OUT_C + i * OUT_C + ob) * NTOK;

#pragma unroll
        for (int oo = 0; oo < OH; ++oo) {
            float sp = 0.0f;
#pragma unroll
            for (int k = 0; k < NB; ++k)
                sp = fmaf(bs[k], __ldcs(wc + (size_t)(oo * NB + k) * NTOK), sp);
            acc[oo] = fmaf(__ldcs(wu + (size_t)oo * NTOK), sp, acc[oo]);
            acc[oo] = fmaf(sx, __ldcs(wr + (size_t)oo * NTOK), acc[oo]);
        }
    }

    float* yp = out + ((size_t)b * OUT_C + ob) * NTOK + n;
#pragma unroll
    for (int oo = 0; oo < OH; ++oo)
        yp[(size_t)oo * NTOK] = acc[oo];
}

extern "C" void kernel_launch(void* const* d_in, const int* in_sizes, int n_in,
                              void* d_out, int out_size) {
    const float* x = (const float*)d_in[0];   // (4, 8, 65536)
    const float* w = (const float*)d_in[1];   // (4, 640, 65536)
    float* out = (float*)d_out;               // (4, 8, 65536)

    const int total = 4 * NTOK;               // 262144 tokens
    dim3 grid(total / 128, OUT_C / OH);       // (2048, 4)
    sepkan_kernel<<<grid, 128>>>(x, w, out);
}